// round 2
// baseline (speedup 1.0000x reference)
#include <cuda_runtime.h>

#define DIM 256
#define BATCH 32768
#define NW 26

typedef unsigned long long ull;

// ---- packed f32x2 helpers (FFMA2 path is PTX-only on sm_103a) ----
__device__ __forceinline__ ull pk2(float lo, float hi) {
    ull r; asm("mov.b64 %0, {%1,%2};" : "=l"(r) : "f"(lo), "f"(hi)); return r;
}
__device__ __forceinline__ float lo2(ull v) {
    float a, b; asm("mov.b64 {%0,%1}, %2;" : "=f"(a), "=f"(b) : "l"(v)); return a;
}
__device__ __forceinline__ float hi2(ull v) {
    float a, b; asm("mov.b64 {%0,%1}, %2;" : "=f"(a), "=f"(b) : "l"(v)); return b;
}
__device__ __forceinline__ ull mul2(ull a, ull b) {
    ull d; asm("mul.rn.f32x2 %0, %1, %2;" : "=l"(d) : "l"(a), "l"(b)); return d;
}
__device__ __forceinline__ ull add2(ull a, ull b) {
    ull d; asm("add.rn.f32x2 %0, %1, %2;" : "=l"(d) : "l"(a), "l"(b)); return d;
}
__device__ __forceinline__ ull fma2(ull a, ull b, ull c) {
    ull d; asm("fma.rn.f32x2 %0, %1, %2, %3;" : "=l"(d) : "l"(a), "l"(b), "l"(c)); return d;
}

// Layout: warp handles 8 samples. Lane L: j = L&7 (amp bits 7..5 of index),
// g = L>>3 selects the sample pair; samples (s0, s0+1) packed lo/hi in f32x2.
// Each lane holds amps i = (j<<5)|k for k=0..31 of both samples.
// Wire w <-> index bit (7-w): wires 0,1,2 = lane bits (shfl masks 4,2,1),
// wires 3..7 = k bits (masks 16,8,4,2,1). State is exactly real throughout.
__global__ __launch_bounds__(256) void qae_kernel(const float* __restrict__ x,
                                                  const float* __restrict__ w,
                                                  float* __restrict__ out) {
    __shared__ float sc[NW], ss[NW];
    int tid = threadIdx.x;
    if (tid < NW) {
        float s, c;
        sincosf(0.5f * w[tid], &s, &c);
        sc[tid] = c; ss[tid] = s;
    }
    __syncthreads();

    int lane = tid & 31;
    int j = lane & 7;
    int g = lane >> 3;
    int warp = (blockIdx.x * blockDim.x + tid) >> 5;
    int s0 = warp * 8 + g * 2;

    ull r[32];
    {
        const float4* p0 = reinterpret_cast<const float4*>(x + (size_t)s0 * DIM + j * 32);
        const float4* p1 = reinterpret_cast<const float4*>(x + (size_t)(s0 + 1) * DIM + j * 32);
        #pragma unroll
        for (int t = 0; t < 8; t++) {
            float4 a = p0[t]; float4 b = p1[t];
            r[t * 4 + 0] = pk2(a.x, b.x);
            r[t * 4 + 1] = pk2(a.y, b.y);
            r[t * 4 + 2] = pk2(a.z, b.z);
            r[t * 4 + 3] = pk2(a.w, b.w);
        }
    }

    // squared input norms (normalization folded into epilogue; rotations are orthogonal)
    ull n2v = 0ull;
    #pragma unroll
    for (int k = 0; k < 32; k++) n2v = fma2(r[k], r[k], n2v);

    // CZ layer parity per amp index i=(j<<5)|k: b0=bit7, b1=bit6,
    // parity = (b0&b1) ^ ((b0^b1) & popc(low 6 bits)&1)  [same formula as R1, verified]
    unsigned czm = 0;
    #pragma unroll
    for (int k = 0; k < 32; k++) {
        int i = (j << 5) | k;
        int b0 = (i >> 7) & 1, b1 = (i >> 6) & 1;
        int rp = __popc(i & 63) & 1;
        czm |= (unsigned)((b0 & b1) ^ ((b0 ^ b1) & rp)) << k;
    }

    #pragma unroll
    for (int l = 0; l < 3; l++) {
        // wires 0..2: cross-lane (lane xor 4,2,1)
        #pragma unroll
        for (int q = 0; q < 3; q++) {
            float c = sc[l * 8 + q], s = ss[l * 8 + q];
            int lm = 4 >> q;
            float se = (lane & lm) ? s : -s;
            ull cv = pk2(c, c), sev = pk2(se, se);
            #pragma unroll
            for (int k = 0; k < 32; k++) {
                ull p = __shfl_xor_sync(0xffffffffu, r[k], lm);
                r[k] = fma2(cv, r[k], mul2(sev, p));
            }
        }
        // wires 3..7: in-register (k xor 16,8,4,2,1)
        #pragma unroll
        for (int q = 0; q < 5; q++) {
            float c = sc[l * 8 + 3 + q], s = ss[l * 8 + 3 + q];
            int m = 16 >> q;
            ull cv = pk2(c, c), sv = pk2(s, s), snv = pk2(-s, -s);
            #pragma unroll
            for (int k = 0; k < 32; k++) {
                if (k & m) continue;
                ull a = r[k], b = r[k | m];
                r[k]     = fma2(cv, a, mul2(snv, b));
                r[k | m] = fma2(cv, b, mul2(sv, a));
            }
        }
        // fused CZ layer: flip sign bit of both packed halves where parity set
        #pragma unroll
        for (int k = 0; k < 32; k++) {
            unsigned sb = ((czm >> k) & 1u) << 31;
            ull msk = ((ull)sb << 32) | (ull)sb;
            r[k] ^= msk;
        }
    }

    // final layer: RY on trash wires 0,1 (weights 24,25), cross-lane masks 4,2
    #pragma unroll
    for (int q = 0; q < 2; q++) {
        float c = sc[24 + q], s = ss[24 + q];
        int lm = 4 >> q;
        float se = (lane & lm) ? s : -s;
        ull cv = pk2(c, c), sev = pk2(se, se);
        #pragma unroll
        for (int k = 0; k < 32; k++) {
            ull p = __shfl_xor_sync(0xffffffffu, r[k], lm);
            r[k] = fma2(cv, r[k], mul2(sev, p));
        }
    }

    // ---- expectations: wire6 -> k bit1, wire7 -> k bit0 (all in-register) ----
    // Off-diagonal sums over half-sets (each pair counted once, x2 at the end).
    // Z terms via norm preservation: <Z> = 1 - 2*S/n2.
    const ull ONE  = 0x3F8000003F800000ull;
    const ull NONE = 0xBF800000BF800000ull;
    ull X6 = 0, X7 = 0, XX = 0, YY = 0, S0v = 0, S1v = 0, SXv = 0;
    #pragma unroll
    for (int k = 0; k < 32; k++) {
        int b0 = k & 1, b1 = (k >> 1) & 1;
        ull v = r[k];
        if (!b1) X6 = fma2(v, r[k ^ 2], X6);
        if (!b0) X7 = fma2(v, r[k ^ 1], X7);
        if (!b0) {
            ull p3 = mul2(v, r[k ^ 3]);
            XX = add2(XX, p3);
            YY = fma2(b1 ? ONE : NONE, p3, YY);  // sign = +1 iff bit1 set (bit0=0 here)
        }
        if (b0 | b1) {
            ull sq = mul2(v, v);
            if (b1) S1v = add2(S1v, sq);
            if (b0) S0v = add2(S0v, sq);
            if (b0 ^ b1) SXv = add2(SXv, sq);
        }
    }
    // reduce over the 8-lane group (masks 4,2,1 stay within group)
    #pragma unroll
    for (int m = 4; m; m >>= 1) {
        n2v = add2(n2v, __shfl_xor_sync(0xffffffffu, n2v, m));
        X6  = add2(X6,  __shfl_xor_sync(0xffffffffu, X6,  m));
        X7  = add2(X7,  __shfl_xor_sync(0xffffffffu, X7,  m));
        XX  = add2(XX,  __shfl_xor_sync(0xffffffffu, XX,  m));
        YY  = add2(YY,  __shfl_xor_sync(0xffffffffu, YY,  m));
        S0v = add2(S0v, __shfl_xor_sync(0xffffffffu, S0v, m));
        S1v = add2(S1v, __shfl_xor_sync(0xffffffffu, S1v, m));
        SXv = add2(SXv, __shfl_xor_sync(0xffffffffu, SXv, m));
    }

    if (j < 2) {
        bool h = (j == 1);
        float n2  = h ? hi2(n2v) : lo2(n2v);
        float x6  = h ? hi2(X6)  : lo2(X6);
        float x7  = h ? hi2(X7)  : lo2(X7);
        float xx  = h ? hi2(XX)  : lo2(XX);
        float yy  = h ? hi2(YY)  : lo2(YY);
        float s0s = h ? hi2(S0v) : lo2(S0v);
        float s1s = h ? hi2(S1v) : lo2(S1v);
        float sxs = h ? hi2(SXv) : lo2(SXv);
        float inv2 = 2.0f / n2;
        float* o = out + (size_t)(s0 + j) * 9;
        o[0] = x6 * inv2;
        o[1] = 0.0f;                      // <Y> on a real state is exactly 0
        o[2] = fmaf(-inv2, s1s, 1.0f);
        o[3] = x7 * inv2;
        o[4] = 0.0f;
        o[5] = fmaf(-inv2, s0s, 1.0f);
        o[6] = xx * inv2;
        o[7] = yy * inv2;
        o[8] = fmaf(-inv2, sxs, 1.0f);
    }
}

extern "C" void kernel_launch(void* const* d_in, const int* in_sizes, int n_in,
                              void* d_out, int out_size) {
    const float* x = (const float*)d_in[0];
    const float* w = (const float*)d_in[1];
    if (n_in >= 2 && in_sizes[0] == NW) { const float* t = x; x = w; w = t; }
    float* out = (float*)d_out;
    // 256 threads = 8 warps = 64 samples per block
    qae_kernel<<<BATCH / 64, 256>>>(x, w, out);
}

// round 3
// speedup vs baseline: 1.3998x; 1.3998x over previous
#include <cuda_runtime.h>

#define DIM 256
#define BATCH 32768
#define NW 26

// Layout: warp = 4 samples, 8 lanes per sample (g = lane>>3 selects sample,
// j = lane&7). Lane holds 32 amps i = (j<<5)|k, k=0..31, scalar fp32.
// Wire w <-> index bit (7-w): wires 0..2 = lane bits (shfl masks 4,2,1),
// wires 3..7 = k bits (masks 16,8,4,2,1). State exactly real throughout.
// RY applied in tan-form (uniform cos factor dropped; normalize by final norm).
__global__ __launch_bounds__(256, 3) void qae_kernel(const float* __restrict__ x,
                                                     const float* __restrict__ w,
                                                     float* __restrict__ out) {
    __shared__ float st[NW];
    int tid = threadIdx.x;
    if (tid < NW) {
        float s, c;
        sincosf(0.5f * w[tid], &s, &c);
        st[tid] = s / c;                    // tan(theta/2)
    }
    __syncthreads();

    int lane = tid & 31;
    int j = lane & 7;
    int g = lane >> 3;
    int warp = (blockIdx.x * blockDim.x + tid) >> 5;
    int smp = warp * 4 + g;

    float r[32];
    {
        const float4* p = reinterpret_cast<const float4*>(x + (size_t)smp * DIM + j * 32);
        #pragma unroll
        for (int t = 0; t < 8; t++) {
            float4 v = p[t];
            r[t * 4 + 0] = v.x; r[t * 4 + 1] = v.y;
            r[t * 4 + 2] = v.z; r[t * 4 + 3] = v.w;
        }
    }

    // CZ layer parity per amp i=(j<<5)|k: b0=bit7, b1=bit6,
    // parity = (b0&b1) ^ ((b0^b1) & popc(low 6 bits)&1)   [verified R1/R2]
    unsigned czm = 0;
    #pragma unroll
    for (int k = 0; k < 32; k++) {
        int i = (j << 5) | k;
        int b0 = (i >> 7) & 1, b1 = (i >> 6) & 1;
        int rp = __popc(i & 63) & 1;
        czm |= (unsigned)((b0 & b1) ^ ((b0 ^ b1) & rp)) << k;
    }

    #pragma unroll
    for (int l = 0; l < 3; l++) {
        // wires 0..2: cross-lane, tan-form: r += (+-t) * partner  (1 FMA/amp)
        #pragma unroll
        for (int q = 0; q < 3; q++) {
            float t = st[l * 8 + q];
            int lm = 4 >> q;
            float se = (lane & lm) ? t : -t;
            #pragma unroll
            for (int k = 0; k < 32; k++) {
                float pv = __shfl_xor_sync(0xffffffffu, r[k], lm);
                r[k] = fmaf(se, pv, r[k]);
            }
        }
        // wires 3..7: in-register, tan-form: a'=a-t*b, b'=b+t*a  (1 FMA/amp)
        #pragma unroll
        for (int q = 0; q < 5; q++) {
            float t = st[l * 8 + 3 + q];
            int m = 16 >> q;
            #pragma unroll
            for (int k = 0; k < 32; k++) {
                if (k & m) continue;
                float a = r[k];
                r[k]     = fmaf(-t, r[k | m], a);
                r[k | m] = fmaf( t, a, r[k | m]);
            }
        }
        // fused CZ layer: flip fp32 sign bit where parity set (ALU pipe)
        #pragma unroll
        for (int k = 0; k < 32; k++) {
            unsigned sb = (czm << (31 - k)) & 0x80000000u;
            r[k] = __uint_as_float(__float_as_uint(r[k]) ^ sb);
        }
    }

    // final layer: RY on trash wires 0,1 -> cross-lane masks 4,2
    #pragma unroll
    for (int q = 0; q < 2; q++) {
        float t = st[24 + q];
        int lm = 4 >> q;
        float se = (lane & lm) ? t : -t;
        #pragma unroll
        for (int k = 0; k < 32; k++) {
            float pv = __shfl_xor_sync(0xffffffffu, r[k], lm);
            r[k] = fmaf(se, pv, r[k]);
        }
    }

    // ---- expectations: wire6 -> k bit1, wire7 -> k bit0 (all in-register) ----
    // Off-diagonal sums over half-sets (x2 at the end). Diagonal terms via
    // per-(b1,b0)-class square sums; final norm replaces input norm (tan-form).
    float X6 = 0, X7 = 0, XX = 0, YY = 0;
    float q0 = 0, q1 = 0, q2 = 0, q3 = 0;   // class (b1<<1)|b0
    #pragma unroll
    for (int k = 0; k < 32; k++) {
        int b0 = k & 1, b1 = (k >> 1) & 1;
        float v = r[k];
        if (!b1) X6 = fmaf(v, r[k ^ 2], X6);
        if (!b0) {
            X7 = fmaf(v, r[k ^ 1], X7);
            float pv = r[k ^ 3];
            XX = fmaf(v, pv, XX);
            YY = b1 ? fmaf(v, pv, YY) : fmaf(-v, pv, YY);
        }
        int cls = k & 3;
        if      (cls == 0) q0 = fmaf(v, v, q0);
        else if (cls == 1) q1 = fmaf(v, v, q1);
        else if (cls == 2) q2 = fmaf(v, v, q2);
        else               q3 = fmaf(v, v, q3);
    }
    // reduce within the 8-lane sample group
    #pragma unroll
    for (int m = 4; m; m >>= 1) {
        X6 += __shfl_xor_sync(0xffffffffu, X6, m);
        X7 += __shfl_xor_sync(0xffffffffu, X7, m);
        XX += __shfl_xor_sync(0xffffffffu, XX, m);
        YY += __shfl_xor_sync(0xffffffffu, YY, m);
        q0 += __shfl_xor_sync(0xffffffffu, q0, m);
        q1 += __shfl_xor_sync(0xffffffffu, q1, m);
        q2 += __shfl_xor_sync(0xffffffffu, q2, m);
        q3 += __shfl_xor_sync(0xffffffffu, q3, m);
    }

    if (j == 0) {
        float n2 = (q0 + q1) + (q2 + q3);   // final state norm^2
        float inv2 = 2.0f / n2;
        float s1 = q2 + q3;                 // b1 (wire6) = 1
        float s0 = q1 + q3;                 // b0 (wire7) = 1
        float sx = q1 + q2;                 // b0 ^ b1 = 1
        float* o = out + (size_t)smp * 9;
        o[0] = X6 * inv2;
        o[1] = 0.0f;                        // <Y> on a real state is exactly 0
        o[2] = fmaf(-inv2, s1, 1.0f);
        o[3] = X7 * inv2;
        o[4] = 0.0f;
        o[5] = fmaf(-inv2, s0, 1.0f);
        o[6] = XX * inv2;
        o[7] = YY * inv2;
        o[8] = fmaf(-inv2, sx, 1.0f);
    }
}

extern "C" void kernel_launch(void* const* d_in, const int* in_sizes, int n_in,
                              void* d_out, int out_size) {
    const float* x = (const float*)d_in[0];
    const float* w = (const float*)d_in[1];
    if (n_in >= 2 && in_sizes[0] == NW) { const float* t = x; x = w; w = t; }
    float* out = (float*)d_out;
    // 256 threads = 8 warps = 32 samples per block
    qae_kernel<<<BATCH / 32, 256>>>(x, w, out);
}

// round 4
// speedup vs baseline: 2.0051x; 1.4324x over previous
#include <cuda_runtime.h>

#define DIM 256
#define BATCH 32768
#define NW 26

typedef unsigned long long ull;

// ---- packed f32x2 helpers (PTX-only path on sm_103a) ----
__device__ __forceinline__ ull pk2(float lo, float hi) {
    ull r; asm("mov.b64 %0, {%1,%2};" : "=l"(r) : "f"(lo), "f"(hi)); return r;
}
__device__ __forceinline__ float lo2(ull v) {
    float a, b; asm("mov.b64 {%0,%1}, %2;" : "=f"(a), "=f"(b) : "l"(v)); return a;
}
__device__ __forceinline__ float hi2(ull v) {
    float a, b; asm("mov.b64 {%0,%1}, %2;" : "=f"(a), "=f"(b) : "l"(v)); return b;
}
__device__ __forceinline__ ull mul2(ull a, ull b) {
    ull d; asm("mul.rn.f32x2 %0, %1, %2;" : "=l"(d) : "l"(a), "l"(b)); return d;
}
__device__ __forceinline__ ull add2(ull a, ull b) {
    ull d; asm("add.rn.f32x2 %0, %1, %2;" : "=l"(d) : "l"(a), "l"(b)); return d;
}
__device__ __forceinline__ ull fma2(ull a, ull b, ull c) {
    ull d; asm("fma.rn.f32x2 %0, %1, %2, %3;" : "=l"(d) : "l"(a), "l"(b), "l"(c)); return d;
}
__device__ __forceinline__ ull swap2(ull v) {  // (lo,hi) -> (hi,lo)
    ull d;
    asm("{\n\t.reg .b32 a,b;\n\tmov.b64 {a,b}, %1;\n\tmov.b64 %0, {b,a};\n\t}"
        : "=l"(d) : "l"(v));
    return d;
}

// Bit layout (index i, 8 bits; wire w <-> bit (7-w)):
//   lane bits: i[3:2] = j (wires 4,5 -> cross-lane, shfl masks 2,1)
//   pack bit:  i[0]   (wire 7 -> lo/hi of f32x2)
//   reg bits:  t[4:0] = { i7 i6 i5 i4 i1 }  (wires 0,1,2,3,6 -> t masks 16,8,4,2,1)
// Warp = 8 samples (g = lane>>2), lane holds 64 amps as 32 ull, scalar-real state.
// RY in tan-form (uniform cos dropped; normalize by final state norm).
__global__ __launch_bounds__(256, 2) void qae_kernel(const float* __restrict__ x,
                                                     const float* __restrict__ w,
                                                     float* __restrict__ out) {
    __shared__ float st[NW];
    int tid = threadIdx.x;
    if (tid < NW) {
        float s, c;
        sincosf(0.5f * w[tid], &s, &c);
        st[tid] = s / c;                         // tan(theta/2)
    }
    __syncthreads();

    int lane = tid & 31;
    int j = lane & 3;
    int g = lane >> 2;
    int warp = (blockIdx.x * blockDim.x + tid) >> 5;
    int smp = warp * 8 + g;

    // Load: float4 #f (f=0..15) at amp i = f*16 + j*4 -> u[2f] = (c0,c1), u[2f+1] = (c2,c3)
    ull u[32];
    {
        const float4* p = reinterpret_cast<const float4*>(x + (size_t)smp * DIM);
        #pragma unroll
        for (int f = 0; f < 16; f++) {
            float4 v = p[f * 4 + j];
            u[2 * f]     = pk2(v.x, v.y);
            u[2 * f + 1] = pk2(v.z, v.w);
        }
    }

    #pragma unroll
    for (int l = 0; l < 3; l++) {
        // wires 0..3: in-register, t masks 16,8,4,2  (1 fma2 per ull per rotation)
        #pragma unroll
        for (int q = 0; q < 4; q++) {
            float t = st[l * 8 + q];
            int m = 16 >> q;
            ull tp = pk2(t, t), tn = pk2(-t, -t);
            #pragma unroll
            for (int k = 0; k < 32; k++) {
                if (k & m) continue;
                ull a = u[k];
                u[k]     = fma2(tn, u[k | m], a);
                u[k | m] = fma2(tp, a, u[k | m]);
            }
        }
        // wires 4,5: cross-lane, lane masks 2,1
        #pragma unroll
        for (int q = 0; q < 2; q++) {
            float t = st[l * 8 + 4 + q];
            int lm = 2 >> q;
            float se = (lane & lm) ? t : -t;
            ull sev = pk2(se, se);
            #pragma unroll
            for (int k = 0; k < 32; k++) {
                ull pv = __shfl_xor_sync(0xffffffffu, u[k], lm);
                u[k] = fma2(sev, pv, u[k]);
            }
        }
        // wire 6: in-register, t mask 1
        {
            float t = st[l * 8 + 6];
            ull tp = pk2(t, t), tn = pk2(-t, -t);
            #pragma unroll
            for (int k = 0; k < 32; k += 2) {
                ull a = u[k];
                u[k]     = fma2(tn, u[k + 1], a);
                u[k + 1] = fma2(tp, a, u[k + 1]);
            }
        }
        // wire 7: pack axis: lo' = lo - t*hi, hi' = hi + t*lo
        {
            float t = st[l * 8 + 7];
            ull ts = pk2(-t, t);
            #pragma unroll
            for (int k = 0; k < 32; k++)
                u[k] = fma2(ts, swap2(u[k]), u[k]);
        }
        // CZ layer: parity(i) = (b0&b1) ^ ((b0^b1) & popc(i[5:0])&1); all compile-time
        #pragma unroll
        for (int k = 0; k < 32; k++) {
            const int b0 = (k >> 4) & 1, b1 = (k >> 3) & 1;   // i7, i6
            const int rp = ((k >> 2) ^ (k >> 1) ^ k) & 1;      // i5^i4^i1 (lane bits: j^(j>>1) -> handled below)
            // lane bits i3,i2 also belong to "rest": their parity = (j ^ (j>>1)) & 1, runtime-uniform
            const int a = b0 & b1, bx = b0 ^ b1;
            int jp = (j ^ (j >> 1)) & 1;                        // parity of lane bits
            int plo = a ^ (bx & (rp ^ jp));
            int phi = a ^ (bx & (rp ^ jp ^ 1));                 // pack bit flips rest parity
            ull msk = ((ull)(unsigned)(phi << 31) << 32) | (unsigned)(plo << 31);
            u[k] ^= msk;
        }
    }

    // final layer: RY on trash wires 0,1 -> in-register masks 16, 8
    #pragma unroll
    for (int q = 0; q < 2; q++) {
        float t = st[24 + q];
        int m = 16 >> q;
        ull tp = pk2(t, t), tn = pk2(-t, -t);
        #pragma unroll
        for (int k = 0; k < 32; k++) {
            if (k & m) continue;
            ull a = u[k];
            u[k]     = fma2(tn, u[k | m], a);
            u[k | m] = fma2(tp, a, u[k | m]);
        }
    }

    // ---- expectations: wire6 = t bit0, wire7 = pack bit ----
    const ull SGN = pk2(-1.0f, 1.0f);
    ull X6 = 0, X7 = 0, XX = 0, YY = 0, QE = 0, QO = 0;
    #pragma unroll
    for (int s = 0; s < 16; s++) {
        ull a = u[2 * s], b = u[2 * s + 1];
        X6 = fma2(a, b, X6);                 // pairs (i, i^2), half-set bit1=0
        ull sa = swap2(a), sb = swap2(b);
        X7 = fma2(a, sa, X7);                // lo*hi per ull (dup in both halves)
        X7 = fma2(b, sb, X7);
        ull prod = mul2(a, sb);              // lo: (00)*(11), hi: (01)*(10)
        XX = add2(XX, prod);
        YY = fma2(SGN, prod, YY);
        QE = fma2(a, a, QE);                 // lo->cls0, hi->cls1
        QO = fma2(b, b, QO);                 // lo->cls2, hi->cls3
    }
    // reduce over the 4-lane sample group
    #pragma unroll
    for (int m = 2; m; m >>= 1) {
        X6 = add2(X6, __shfl_xor_sync(0xffffffffu, X6, m));
        X7 = add2(X7, __shfl_xor_sync(0xffffffffu, X7, m));
        XX = add2(XX, __shfl_xor_sync(0xffffffffu, XX, m));
        YY = add2(YY, __shfl_xor_sync(0xffffffffu, YY, m));
        QE = add2(QE, __shfl_xor_sync(0xffffffffu, QE, m));
        QO = add2(QO, __shfl_xor_sync(0xffffffffu, QO, m));
    }

    if (j == 0) {
        float q0 = lo2(QE), q1 = hi2(QE), q2 = lo2(QO), q3 = hi2(QO);
        float n2 = (q0 + q1) + (q2 + q3);    // final-state norm^2 (tan-form scale)
        float inv2 = 2.0f / n2;
        float s1 = q2 + q3;                  // wire6 bit = 1
        float s0 = q1 + q3;                  // wire7 bit = 1
        float sx = q1 + q2;                  // bits differ
        float* o = out + (size_t)smp * 9;
        o[0] = (lo2(X6) + hi2(X6)) * inv2;
        o[1] = 0.0f;                         // <Y> on a real state is exactly 0
        o[2] = fmaf(-inv2, s1, 1.0f);
        o[3] = lo2(X7) * inv2;               // both halves hold the full sum
        o[4] = 0.0f;
        o[5] = fmaf(-inv2, s0, 1.0f);
        o[6] = (lo2(XX) + hi2(XX)) * inv2;
        o[7] = (lo2(YY) + hi2(YY)) * inv2;
        o[8] = fmaf(-inv2, sx, 1.0f);
    }
}

extern "C" void kernel_launch(void* const* d_in, const int* in_sizes, int n_in,
                              void* d_out, int out_size) {
    const float* x = (const float*)d_in[0];
    const float* w = (const float*)d_in[1];
    if (n_in >= 2 && in_sizes[0] == NW) { const float* t = x; x = w; w = t; }
    float* out = (float*)d_out;
    // 256 threads = 8 warps = 64 samples per block
    qae_kernel<<<BATCH / 64, 256>>>(x, w, out);
}